// round 12
// baseline (speedup 1.0000x reference)
#include <cuda_runtime.h>
#include <math.h>
#include <stdint.h>

// Problem constants
#define TK   16384
#define HD   7168
#define NE   256
#define BM   128            // tokens per CTA (GEMM)
#define BK   64             // k-chunk int8 (64B rows)
#define NCH  (HD / BK)      // 112
#define NPAIR 4             // (0,0) (0,1) (1,0) (1,1)
#define CAP  8192           // flagged-token capacity

// Margin thresholds (~8 sigma of int8-path score noise, sigma_margin ~3e-5).
// TAU_ORDER gates min adjacent gap within the ordered top-8 AND the 8/9 gap
// (top_k output is order-sensitive!). TAU_GROUP gates the group-4/5 gap.
#define TAU_ORDER  2.5e-4f
#define TAU_GROUP  5e-4f

// GEMM smem: 2 stages x { A: 128x80B, B: 256x80B }
#define ROWB     80
#define A_TILE   (128 * ROWB)
#define B_TILE   (256 * ROWB)
#define STAGE_SZ (A_TILE + B_TILE)
#define SMEM_TOTAL (2 * STAGE_SZ)        // 61440

static __device__ int8_t g_Xs[2][(size_t)TK * HD];    // 2 x 117 MB
static __device__ int8_t g_Ws[2][(size_t)NE * HD];
static __device__ int    g_S[NPAIR][(size_t)TK * NE]; // 4 x 16.8 MB
static __device__ int    g_flagCnt;
static __device__ int    g_flagList[CAP];
static __device__ float  g_Lfix[(size_t)CAP * NE];    // 8.4 MB

__constant__ int c_PI[NPAIR] = {0, 0, 1, 1};
__constant__ int c_PJ[NPAIR] = {0, 1, 0, 1};

// ---------------------------------------------------------------------------
__device__ __forceinline__ uint32_t smem_u32(const void* p) {
    uint32_t a;
    asm("{ .reg .u64 t; cvta.to.shared.u64 t, %1; cvt.u32.u64 %0, t; }"
        : "=r"(a) : "l"(p));
    return a;
}
#define LDSM_X4(R0, R1, R2, R3, ADDR) \
    asm volatile("ldmatrix.sync.aligned.m8n8.x4.shared.b16 {%0,%1,%2,%3}, [%4];" \
                 : "=r"(R0), "=r"(R1), "=r"(R2), "=r"(R3) : "r"(ADDR))
#define MMA_S8(C, A, B0, B1) \
    asm volatile("mma.sync.aligned.m16n8k32.row.col.s32.s8.s8.s32 " \
                 "{%0,%1,%2,%3}, {%4,%5,%6,%7}, {%8,%9}, {%0,%1,%2,%3};" \
                 : "+r"((C)[0]), "+r"((C)[1]), "+r"((C)[2]), "+r"((C)[3]) \
                 : "r"((A)[0]), "r"((A)[1]), "r"((A)[2]), "r"((A)[3]), \
                   "r"(B0), "r"(B1))
#define CP_ASYNC16(DST, SRC) \
    asm volatile("cp.async.cg.shared.global [%0], [%1], 16;" \
                 :: "r"(DST), "l"(SRC) : "memory")
#define CP_COMMIT() asm volatile("cp.async.commit_group;" ::: "memory")
#define CP_WAIT1()  asm volatile("cp.async.wait_group 1;" ::: "memory")

// Fast-math-immune ~1-ulp sigmoid (proved necessary in R3)
__device__ __forceinline__ float sigmoid_acc(float x)
{
    float t = -x;
    t = fminf(fmaxf(t, -80.0f), 80.0f);
    float n = rintf(t * 1.4426950408889634f);
    float r = fmaf(n, -0.693359375f, t);
    r = fmaf(n, 2.12194440e-4f, r);
    float p = 1.9841270e-4f;
    p = fmaf(p, r, 1.3888889e-3f);
    p = fmaf(p, r, 8.3333333e-3f);
    p = fmaf(p, r, 4.1666667e-2f);
    p = fmaf(p, r, 0.16666667f);
    p = fmaf(p, r, 0.5f);
    p = fmaf(p, r, 1.0f);
    p = fmaf(p, r, 1.0f);
    float e = p * __int_as_float(((int)n + 127) << 23);
    return __frcp_rn(1.0f + e);
}

// ---------------------------------------------------------------------------
// ROUTING CORE. m_order = min(adjacent gaps within ordered top-8, v8-v9);
// m_group = group-4/5 gap. Both must clear their tau or the token is unsafe.
// ---------------------------------------------------------------------------
__device__ __forceinline__ void route_token(
    const float lgv[8], const float* __restrict__ BIAS, int tok,
    float* __restrict__ out, int tx, float* m_group, float* m_order)
{
    const unsigned FULL = 0xffffffffu;
    float sfc[8];
    #pragma unroll
    for (int g = 0; g < 8; g++)
        sfc[g] = sigmoid_acc(lgv[g]) + __ldg(&BIAS[g * 32 + tx]);

    float gs[8];
    #pragma unroll
    for (int g = 0; g < 8; g++) {
        float m1 = sfc[g], m2 = -3.4e38f;
        #pragma unroll
        for (int off = 16; off > 0; off >>= 1) {
            float o1 = __shfl_xor_sync(FULL, m1, off);
            float o2 = __shfl_xor_sync(FULL, m2, off);
            if (o1 > m1) { m2 = fmaxf(m1, o2); m1 = o1; }
            else         { m2 = fmaxf(m2, o1); }
        }
        gs[g] = m1 + m2;
    }

    unsigned gmask = 0; float g4v = 0.0f;
    #pragma unroll
    for (int it = 0; it < 4; it++) {
        float best = -3.4e38f; int bg = 0;
        #pragma unroll
        for (int g = 0; g < 8; g++) {
            bool fr = !((gmask >> g) & 1);
            if (fr && gs[g] > best) { best = gs[g]; bg = g; }
        }
        gmask |= (1u << bg);
        g4v = best;
    }
    // 5th-best group for margin
    {
        float best = -3.4e38f;
        #pragma unroll
        for (int g = 0; g < 8; g++) {
            bool fr = !((gmask >> g) & 1);
            if (fr && gs[g] > best) best = gs[g];
        }
        *m_group = g4v - best;
    }

    float val[8];
    #pragma unroll
    for (int g = 0; g < 8; g++)
        val[g] = ((gmask >> g) & 1) ? sfc[g] : 0.0f;

    float wts[8]; int ids[8]; float wsum = 0.0f;
    float prev_bv = 0.0f, v8 = 0.0f, madj = 3.4e38f;
    #pragma unroll
    for (int k = 0; k < 8; k++) {
        float bv = -3.4e38f; int be = 1 << 30;
        #pragma unroll
        for (int g = 0; g < 8; g++) {
            int e = g * 32 + tx;
            bool better = (val[g] > bv) || (val[g] == bv && e < be);
            if (better) { bv = val[g]; be = e; }
        }
        #pragma unroll
        for (int off = 16; off > 0; off >>= 1) {
            float ov = __shfl_xor_sync(FULL, bv, off);
            int   oe = __shfl_xor_sync(FULL, be, off);
            if (ov > bv || (ov == bv && oe < be)) { bv = ov; be = oe; }
        }
        if (k > 0) madj = fminf(madj, prev_bv - bv);   // adjacent order gap
        prev_bv = bv;
        const int cg = be >> 5, cl = be & 31;
        float sel = lgv[0];
        #pragma unroll
        for (int g = 1; g < 8; g++) if (g == cg) sel = lgv[g];
        float lg = __shfl_sync(FULL, sel, cl);
        float wgt = sigmoid_acc(lg);
        wts[k] = wgt; ids[k] = be; wsum += wgt; v8 = bv;
        #pragma unroll
        for (int g = 0; g < 8; g++)
            if (g == cg && tx == cl) val[g] = -3.4e38f;
    }
    // 9th-best expert: include the 8/9 boundary in the order margin
    {
        float bv = -3.4e38f;
        #pragma unroll
        for (int g = 0; g < 8; g++) if (val[g] > bv) bv = val[g];
        #pragma unroll
        for (int off = 16; off > 0; off >>= 1)
            bv = fmaxf(bv, __shfl_xor_sync(FULL, bv, off));
        madj = fminf(madj, v8 - bv);
    }
    *m_order = madj;

    if (tx == 0) {
        float denom = wsum + 1e-20f;
        #pragma unroll
        for (int k = 0; k < 8; k++) {
            out[(size_t)tok * 8 + k] = (float)ids[k];
            out[(size_t)TK * 8 + (size_t)tok * 8 + k] = (wts[k] / denom) * 2.5f;
        }
    }
}

// ---------------------------------------------------------------------------
// Kernel 0: zero flag counter
__global__ void zero_kernel() { if (threadIdx.x == 0) g_flagCnt = 0; }

// 2-level int8 slicing (scales power-of-two, ratio 128)
__device__ __forceinline__ void slice2(float x, float inv_s, float s,
                                       signed char& o0, signed char& o1)
{
    float c0 = rintf(x * inv_s);
    c0 = fminf(fmaxf(c0, -127.0f), 127.0f);
    float r1 = fmaf(c0, -s, x);
    float c1 = rintf(r1 * (inv_s * 128.0f));
    c1 = fminf(fmaxf(c1, -127.0f), 127.0f);
    o0 = (signed char)(int)c0; o1 = (signed char)(int)c1;
}

__global__ void split_x_kernel(const float* __restrict__ X)
{
    size_t i4 = ((size_t)blockIdx.x * blockDim.x + threadIdx.x) * 4;
    if (i4 >= (size_t)TK * HD) return;
    float4 v = *(const float4*)(X + i4);
    char4 p[2];
    slice2(v.x, 16.0f, 0.0625f, p[0].x, p[1].x);
    slice2(v.y, 16.0f, 0.0625f, p[0].y, p[1].y);
    slice2(v.z, 16.0f, 0.0625f, p[0].z, p[1].z);
    slice2(v.w, 16.0f, 0.0625f, p[0].w, p[1].w);
    *(char4*)(&g_Xs[0][i4]) = p[0];
    *(char4*)(&g_Xs[1][i4]) = p[1];
}

__global__ void split_w_kernel(const float* __restrict__ W)
{
    size_t i4 = ((size_t)blockIdx.x * blockDim.x + threadIdx.x) * 4;
    if (i4 >= (size_t)NE * HD) return;
    float4 v = *(const float4*)(W + i4);
    const float inv_s = 8192.0f, s = 1.220703125e-4f;
    char4 p[2];
    slice2(v.x, inv_s, s, p[0].x, p[1].x);
    slice2(v.y, inv_s, s, p[0].y, p[1].y);
    slice2(v.z, inv_s, s, p[0].z, p[1].z);
    slice2(v.w, inv_s, s, p[0].w, p[1].w);
    *(char4*)(&g_Ws[0][i4]) = p[0];
    *(char4*)(&g_Ws[1][i4]) = p[1];
}

// ---------------------------------------------------------------------------
// Kernel 2: exact s8 pair GEMMs (grid.z = 4).
// ---------------------------------------------------------------------------
__global__ __launch_bounds__(512, 1)
void pair_gemm_kernel()
{
    extern __shared__ char smem[];
    const uint32_t smb = smem_u32(smem);
    const int tid = threadIdx.x;
    const int wid = tid >> 5;
    const int lid = tid & 31;
    const int wm  = wid & 3;
    const int wn  = wid >> 2;
    const int t0  = blockIdx.x * BM;
    const int z   = blockIdx.z;

    const int8_t* Ap = g_Xs[c_PI[z]];
    const int8_t* Bp = g_Ws[c_PJ[z]];

    int acc[2][8][4];
    #pragma unroll
    for (int mt = 0; mt < 2; mt++)
        #pragma unroll
        for (int nt = 0; nt < 8; nt++)
            #pragma unroll
            for (int q = 0; q < 4; q++) acc[mt][nt][q] = 0;

    const uint32_t laneMat = (uint32_t)((lid & 15) * ROWB + (lid >> 4) * 16);

    auto issue = [&](int c, int st) {
        const uint32_t abase = smb + st * STAGE_SZ;
        const uint32_t bbase = abase + A_TILE;
        {
            int row = tid >> 2, seg = tid & 3;
            const void* src = Ap + (size_t)(t0 + row) * HD + c * BK + seg * 16;
            CP_ASYNC16(abase + row * ROWB + seg * 16, src);
        }
        #pragma unroll
        for (int i = 0; i < 2; i++) {
            int idx = tid + 512 * i;
            int row = idx >> 2, seg = idx & 3;
            const void* src = Bp + (size_t)row * HD + c * BK + seg * 16;
            CP_ASYNC16(bbase + row * ROWB + seg * 16, src);
        }
    };

    auto compute = [&](int st) {
        const uint32_t abase = smb + st * STAGE_SZ;
        const uint32_t bbase = abase + A_TILE;
        #pragma unroll
        for (int ks = 0; ks < 2; ks++) {
            const uint32_t kb = ks * 32;
            uint32_t af[2][4];
            #pragma unroll
            for (int mt = 0; mt < 2; mt++) {
                uint32_t ad = abase + (wm * 32 + mt * 16) * ROWB + kb + laneMat;
                LDSM_X4(af[mt][0], af[mt][1], af[mt][2], af[mt][3], ad);
            }
            uint32_t bf[8][2];
            #pragma unroll
            for (int np = 0; np < 4; np++) {
                uint32_t bd = bbase + (wn * 64 + np * 16) * ROWB + kb + laneMat;
                uint32_t m0, m1, m2, m3;
                LDSM_X4(m0, m1, m2, m3, bd);
                bf[2 * np][0] = m0; bf[2 * np + 1][0] = m1;
                bf[2 * np][1] = m2; bf[2 * np + 1][1] = m3;
            }
            #pragma unroll
            for (int mt = 0; mt < 2; mt++)
                #pragma unroll
                for (int nt = 0; nt < 8; nt++)
                    MMA_S8(acc[mt][nt], af[mt], bf[nt][0], bf[nt][1]);
        }
    };

    issue(0, 0);
    CP_COMMIT();
    for (int c = 0; c < NCH; c++) {
        const int st = c & 1;
        if (c + 1 < NCH) issue(c + 1, st ^ 1);
        CP_COMMIT();
        CP_WAIT1();
        __syncthreads();
        compute(st);
        __syncthreads();
    }

    int* Sz = g_S[z];
    #pragma unroll
    for (int mt = 0; mt < 2; mt++)
        #pragma unroll
        for (int nt = 0; nt < 8; nt++) {
            int r = wm * 32 + mt * 16 + (lid >> 2);
            int n = wn * 64 + nt * 8 + 2 * (lid & 3);
            int* d1 = Sz + (size_t)(t0 + r) * NE + n;
            d1[0] = acc[mt][nt][0];
            d1[1] = acc[mt][nt][1];
            int* d2 = Sz + (size_t)(t0 + r + 8) * NE + n;
            d2[0] = acc[mt][nt][2];
            d2[1] = acc[mt][nt][3];
        }
}

// ---------------------------------------------------------------------------
// Kernel 3: reconstruct + route + flag near-ties (order OR set boundaries)
// logit = 2^-31 * (S00<<14 + (S01+S10)<<7 + S11)
// ---------------------------------------------------------------------------
__global__ __launch_bounds__(256, 4)
void moe_route_kernel(const float* __restrict__ BIAS, float* __restrict__ out)
{
    const int wid = threadIdx.x >> 5;
    const int tx  = threadIdx.x & 31;
    const unsigned FULL = 0xffffffffu;
    const double SC = 1.0 / 2147483648.0;   // 2^-31, exact

    for (int rr = 0; rr < 4; rr++) {
        const int tok = blockIdx.x * 32 + wid * 4 + rr;
        const int* S0 = g_S[0] + (size_t)tok * NE;
        const int* S1 = g_S[1] + (size_t)tok * NE;
        const int* S2 = g_S[2] + (size_t)tok * NE;
        const int* S3 = g_S[3] + (size_t)tok * NE;

        float lgv[8];
        #pragma unroll
        for (int g = 0; g < 8; g++) {
            int e = g * 32 + tx;
            long long L = ((long long)__ldg(&S0[e]) << 14)
                        + ((long long)(__ldg(&S1[e]) + __ldg(&S2[e])) << 7)
                        +  (long long)__ldg(&S3[e]);
            lgv[g] = (float)((double)L * SC);
        }

        float mg, mo;
        route_token(lgv, BIAS, tok, out, tx, &mg, &mo);

        if (tx == 0 && (mg < TAU_GROUP || mo < TAU_ORDER)) {
            int idx = atomicAdd(&g_flagCnt, 1);
            if (idx < CAP) g_flagList[idx] = tok;
        }
        __syncwarp(FULL);
    }
}

// ---------------------------------------------------------------------------
// Kernel 4: recompute flagged-token logits with R3's BIT-EXACT fmaf chain
// (chunk of 32 -> mid of 8 chunks -> total, k ascending).
// grid (CAP/32, NE/32); CTA = 32 flagged tokens x 32 experts.
// ---------------------------------------------------------------------------
__global__ __launch_bounds__(256, 2)
void recompute_kernel(const float* __restrict__ X, const float* __restrict__ W)
{
    __shared__ float Xs[2][32][33];
    __shared__ float Ws[2][32][33];

    const int F = min(g_flagCnt, CAP);
    const int bx = blockIdx.x;
    if (bx * 32 >= F) return;

    const int tid = threadIdx.x;
    const int wid = tid >> 5;
    const int lid = tid & 31;
    const int e0  = blockIdx.y * 32;      // expert block (32 experts)
    const int eB  = e0 + wid * 4;         // this warp's 4 experts

    int slot = bx * 32 + lid;

    float cacc[4], mid[4], acc[4];
    #pragma unroll
    for (int q = 0; q < 4; q++) { mid[q] = 0.0f; acc[q] = 0.0f; }

    // load mapping: 256 threads; X: 32 rows x 32 floats -> thread loads 4
    const int lr = tid >> 3;              // row 0..31
    const int lk = (tid & 7) * 4;         // k offset
    int tokR;
    {
        int s2 = bx * 32 + lr;
        tokR = (s2 < F) ? g_flagList[s2] : g_flagList[0];
    }
    const float* xrow = X + (size_t)tokR * HD + lk;
    const float* wrow = W + (size_t)(e0 + lr) * HD + lk;

    float4 xpf = *(const float4*)(xrow);
    float4 wpf = *(const float4*)(wrow);

    for (int c = 0; c < 224; c++) {
        const int buf = c & 1;
        // scalar stores: rows are 33 floats (132B) -> NOT float4-aligned
        Xs[buf][lr][lk + 0] = xpf.x;
        Xs[buf][lr][lk + 1] = xpf.y;
        Xs[buf][lr][lk + 2] = xpf.z;
        Xs[buf][lr][lk + 3] = xpf.w;
        Ws[buf][lr][lk + 0] = wpf.x;
        Ws[buf][lr][lk + 1] = wpf.y;
        Ws[buf][lr][lk + 2] = wpf.z;
        Ws[buf][lr][lk + 3] = wpf.w;
        __syncthreads();
        if (c + 1 < 224) {
            xpf = *(const float4*)(xrow + (c + 1) * 32);
            wpf = *(const float4*)(wrow + (c + 1) * 32);
        }

        #pragma unroll
        for (int q = 0; q < 4; q++) cacc[q] = 0.0f;
        #pragma unroll 8
        for (int k = 0; k < 32; k++) {
            float xv = Xs[buf][lid][k];
            #pragma unroll
            for (int q = 0; q < 4; q++)
                cacc[q] = fmaf(xv, Ws[buf][wid * 4 + q][k], cacc[q]);
        }
        #pragma unroll
        for (int q = 0; q < 4; q++) mid[q] += cacc[q];
        if ((c & 7) == 7) {
            #pragma unroll
            for (int q = 0; q < 4; q++) { acc[q] += mid[q]; mid[q] = 0.0f; }
        }
        __syncthreads();
    }

    if (slot < F) {
        #pragma unroll
        for (int q = 0; q < 4; q++)
            g_Lfix[(size_t)slot * NE + eB + q] = acc[q];
    }
}

// ---------------------------------------------------------------------------
// Kernel 5: re-route flagged tokens from bit-exact logits, overwrite out
// ---------------------------------------------------------------------------
__global__ __launch_bounds__(256, 4)
void route_fix_kernel(const float* __restrict__ BIAS, float* __restrict__ out)
{
    const int F = min(g_flagCnt, CAP);
    const int wid = threadIdx.x >> 5;
    const int tx  = threadIdx.x & 31;

    for (int rr = 0; rr < 4; rr++) {
        const int slot = blockIdx.x * 32 + wid * 4 + rr;
        if (slot >= F) continue;
        const int tok = g_flagList[slot];
        const float* L = g_Lfix + (size_t)slot * NE;

        float lgv[8];
        #pragma unroll
        for (int g = 0; g < 8; g++) lgv[g] = L[g * 32 + tx];

        float mg, mo;
        route_token(lgv, BIAS, tok, out, tx, &mg, &mo);
    }
}

extern "C" void kernel_launch(void* const* d_in, const int* in_sizes, int n_in,
                              void* d_out, int out_size)
{
    const float* X    = (const float*)d_in[0];
    const float* W    = (const float*)d_in[1];
    const float* BIAS = (const float*)d_in[2];
    float* out = (float*)d_out;

    cudaFuncSetAttribute(pair_gemm_kernel,
                         cudaFuncAttributeMaxDynamicSharedMemorySize, SMEM_TOTAL);

    zero_kernel<<<1, 32>>>();
    split_x_kernel<<<(int)(((size_t)TK * HD / 4 + 255) / 256), 256>>>(X);
    split_w_kernel<<<(int)(((size_t)NE * HD / 4 + 255) / 256), 256>>>(W);
    dim3 grid(TK / BM, 1, NPAIR);
    pair_gemm_kernel<<<grid, 512, SMEM_TOTAL>>>();
    moe_route_kernel<<<TK / 32, 256>>>(BIAS, out);
    dim3 rgrid(CAP / 32, NE / 32);
    recompute_kernel<<<rgrid, 256>>>(X, W);
    route_fix_kernel<<<CAP / 32, 256>>>(BIAS, out);
}

// round 13
// speedup vs baseline: 1.5935x; 1.5935x over previous
#include <cuda_runtime.h>
#include <math.h>
#include <stdint.h>

// Problem constants
#define TK   16384
#define HD   7168
#define NE   256
#define BT   128            // tokens per CTA
#define BE   64             // experts per CTA
#define BK   32             // k-chunk
#define NCH  (HD / BK)      // 224

// smem (floats): A [2][32][132], B [2][32][68]
#define AP    132
#define BP    68
#define A_ST  (32 * AP)                 // 4224 floats per stage
#define B_ST  (32 * BP)                 // 2176
#define SMEM_FLOATS (2 * A_ST + 2 * B_ST)   // 12800 floats = 51200 B

static __device__ float g_L[(size_t)TK * NE];   // fp32 logits scratch (16.8 MB)

// ---------------------------------------------------------------------------
// Packed fp32 (f32x2) helpers — Blackwell-native, both lanes IEEE RN.
// ---------------------------------------------------------------------------
#define FMA2(c, a, b) \
    asm("fma.rn.f32x2 %0, %1, %2, %0;" : "+l"(c) : "l"(a), "l"(b))
#define ADD2(c, s) \
    asm("add.rn.f32x2 %0, %1, %0;" : "+l"(c) : "l"(s))
#define PACK2(o, f) \
    asm("mov.b64 %0, {%1, %1};" : "=l"(o) : "r"(__float_as_uint(f)))

// Fast-math-immune ~1-ulp sigmoid (proved necessary in R3)
__device__ __forceinline__ float sigmoid_acc(float x)
{
    float t = -x;
    t = fminf(fmaxf(t, -80.0f), 80.0f);
    float n = rintf(t * 1.4426950408889634f);
    float r = fmaf(n, -0.693359375f, t);
    r = fmaf(n, 2.12194440e-4f, r);
    float p = 1.9841270e-4f;
    p = fmaf(p, r, 1.3888889e-3f);
    p = fmaf(p, r, 8.3333333e-3f);
    p = fmaf(p, r, 4.1666667e-2f);
    p = fmaf(p, r, 0.16666667f);
    p = fmaf(p, r, 0.5f);
    p = fmaf(p, r, 1.0f);
    p = fmaf(p, r, 1.0f);
    float e = p * __int_as_float(((int)n + 127) << 23);
    return __frcp_rn(1.0f + e);
}

// ---------------------------------------------------------------------------
// Kernel 1: fp32 GEMM via fma.rn.f32x2, accumulation chain BIT-IDENTICAL to
// the R3 passing kernel: per logit, cacc over 32 ascending k (fmaf RN),
// mid += cacc per chunk, acc += mid every 8 chunks. f32x2 = two independent
// RN lanes, so each logit's bit pattern matches R3 exactly.
// CTA: 128 tokens x 64 experts; 256 threads; thread tile 4 tok x 8 exp.
// Warp w (tid>>5) owns experts 8w..8w+7 (B reads broadcast); lane = token grp.
// ---------------------------------------------------------------------------
__global__ __launch_bounds__(256, 1)
void gemm_kernel(const float* __restrict__ X, const float* __restrict__ W,
                 float* __restrict__ L)
{
    extern __shared__ float sm[];
    float* A_s = sm;                 // 2 stages of [32][132]
    float* B_s = sm + 2 * A_ST;      // 2 stages of [32][68]

    const int tid = threadIdx.x;
    const int tg  = tid & 31;        // token group: tokens 4tg..4tg+3
    const int wid = tid >> 5;        // expert group: experts 8wid..8wid+7
    const int t0  = blockIdx.x * BT;
    const int e0  = blockIdx.y * BE;

    // accumulators: [token][expert-pair] as f32x2
    uint64_t acc[4][4], mid[4][4];
    #pragma unroll
    for (int t = 0; t < 4; t++)
        #pragma unroll
        for (int p = 0; p < 4; p++) { acc[t][p] = 0ull; mid[t][p] = 0ull; }

    // A staging: thread covers token atok, k-half akseg (16 floats)
    const int atok  = tid >> 1;
    const int akseg = tid & 1;
    const float* arow = X + (size_t)(t0 + atok) * HD + akseg * 16;

    // B staging: 2 slots; slot s: idx = tid + 256 s; e = idx>>3, seg = idx&7
    const int be0 = (tid + 0)   >> 3, bs0 = (tid + 0)   & 7;
    const int be1 = (tid + 256) >> 3, bs1 = (tid + 256) & 7;
    const float* brow0 = W + (size_t)(e0 + be0) * HD + bs0 * 4;
    const float* brow1 = W + (size_t)(e0 + be1) * HD + bs1 * 4;

    float4 areg[4], breg[2];
    #pragma unroll
    for (int j = 0; j < 4; j++) areg[j] = *(const float4*)(arow + j * 4);
    breg[0] = *(const float4*)(brow0);
    breg[1] = *(const float4*)(brow1);

    for (int c = 0; c < NCH; c++) {
        const int buf = c & 1;
        float* Ab = A_s + buf * A_ST;
        float* Bb = B_s + buf * B_ST;

        // commit staged A (transpose to [k][tok]; 2-way bank conflict, minor)
        #pragma unroll
        for (int j = 0; j < 4; j++) {
            const int kb = akseg * 16 + j * 4;
            Ab[(kb + 0) * AP + atok] = areg[j].x;
            Ab[(kb + 1) * AP + atok] = areg[j].y;
            Ab[(kb + 2) * AP + atok] = areg[j].z;
            Ab[(kb + 3) * AP + atok] = areg[j].w;
        }
        // commit staged B (transpose to [k][e])
        {
            const int k0 = bs0 * 4;
            Bb[(k0 + 0) * BP + be0] = breg[0].x;
            Bb[(k0 + 1) * BP + be0] = breg[0].y;
            Bb[(k0 + 2) * BP + be0] = breg[0].z;
            Bb[(k0 + 3) * BP + be0] = breg[0].w;
            const int k1 = bs1 * 4;
            Bb[(k1 + 0) * BP + be1] = breg[1].x;
            Bb[(k1 + 1) * BP + be1] = breg[1].y;
            Bb[(k1 + 2) * BP + be1] = breg[1].z;
            Bb[(k1 + 3) * BP + be1] = breg[1].w;
        }
        __syncthreads();

        // prefetch next chunk
        if (c + 1 < NCH) {
            const int off = (c + 1) * BK;
            #pragma unroll
            for (int j = 0; j < 4; j++)
                areg[j] = *(const float4*)(arow + off + j * 4);
            breg[0] = *(const float4*)(brow0 + off);
            breg[1] = *(const float4*)(brow1 + off);
        }

        // compute: chunk-local cacc (zeroed), ascending k — R3's exact chain
        uint64_t cacc[4][4];
        #pragma unroll
        for (int t = 0; t < 4; t++)
            #pragma unroll
            for (int p = 0; p < 4; p++) cacc[t][p] = 0ull;

        #pragma unroll 8
        for (int k = 0; k < BK; k++) {
            const float4 a4 = *(const float4*)(Ab + k * AP + 4 * tg);
            uint64_t a2[4];
            PACK2(a2[0], a4.x); PACK2(a2[1], a4.y);
            PACK2(a2[2], a4.z); PACK2(a2[3], a4.w);
            const ulonglong2 b01 = *(const ulonglong2*)(Bb + k * BP + 8 * wid);
            const ulonglong2 b23 = *(const ulonglong2*)(Bb + k * BP + 8 * wid + 4);
            const uint64_t b[4] = {b01.x, b01.y, b23.x, b23.y};
            #pragma unroll
            for (int t = 0; t < 4; t++)
                #pragma unroll
                for (int p = 0; p < 4; p++)
                    FMA2(cacc[t][p], a2[t], b[p]);
        }

        // mid += cacc; acc += mid every 8 chunks (R3's fold schedule)
        #pragma unroll
        for (int t = 0; t < 4; t++)
            #pragma unroll
            for (int p = 0; p < 4; p++) ADD2(mid[t][p], cacc[t][p]);
        if ((c & 7) == 7) {
            #pragma unroll
            for (int t = 0; t < 4; t++)
                #pragma unroll
                for (int p = 0; p < 4; p++) {
                    ADD2(acc[t][p], mid[t][p]);
                    mid[t][p] = 0ull;
                }
        }
        __syncthreads();
    }

    // epilogue: unpack f32x2 lanes -> logits
    #pragma unroll
    for (int t = 0; t < 4; t++)
        #pragma unroll
        for (int p = 0; p < 4; p++) {
            uint32_t lo = (uint32_t)acc[t][p];
            uint32_t hi = (uint32_t)(acc[t][p] >> 32);
            float* dst = L + (size_t)(t0 + 4 * tg + t) * NE + e0 + 8 * wid + 2 * p;
            dst[0] = __uint_as_float(lo);
            dst[1] = __uint_as_float(hi);
        }
}

// ---------------------------------------------------------------------------
// Kernel 2: routing (ops identical to R3). Warp routes a token; lane tx owns
// experts g*32+tx.
// ---------------------------------------------------------------------------
__global__ __launch_bounds__(256, 4)
void route_kernel(const float* __restrict__ BIAS, float* __restrict__ out)
{
    const int wid = threadIdx.x >> 5;
    const int tx  = threadIdx.x & 31;
    const unsigned FULL = 0xffffffffu;

    for (int rr = 0; rr < 4; rr++) {
        const int tok = blockIdx.x * 32 + wid * 4 + rr;
        const float* Lrow = g_L + (size_t)tok * NE;

        float lgv[8], sfc[8];
        #pragma unroll
        for (int g = 0; g < 8; g++) {
            lgv[g] = Lrow[g * 32 + tx];
            sfc[g] = sigmoid_acc(lgv[g]) + __ldg(&BIAS[g * 32 + tx]);
        }

        // per-group score = sum of top-2 within group
        float gs[8];
        #pragma unroll
        for (int g = 0; g < 8; g++) {
            float m1 = sfc[g], m2 = -3.4e38f;
            #pragma unroll
            for (int off = 16; off > 0; off >>= 1) {
                float o1 = __shfl_xor_sync(FULL, m1, off);
                float o2 = __shfl_xor_sync(FULL, m2, off);
                if (o1 > m1) { m2 = fmaxf(m1, o2); m1 = o1; }
                else         { m2 = fmaxf(m2, o1); }
            }
            gs[g] = m1 + m2;
        }

        // top-4 groups (ties -> lower group index)
        unsigned gmask = 0;
        #pragma unroll
        for (int it = 0; it < 4; it++) {
            float best = -3.4e38f; int bg = 0;
            #pragma unroll
            for (int g = 0; g < 8; g++) {
                bool fr = !((gmask >> g) & 1);
                if (fr && gs[g] > best) { best = gs[g]; bg = g; }
            }
            gmask |= (1u << bg);
        }

        float val[8];
        #pragma unroll
        for (int g = 0; g < 8; g++)
            val[g] = ((gmask >> g) & 1) ? sfc[g] : 0.0f;

        // iterative top-8 (descending, ties -> lower expert index)
        float wts[8]; int ids[8]; float wsum = 0.0f;
        #pragma unroll
        for (int k = 0; k < 8; k++) {
            float bv = -3.4e38f; int be = 1 << 30;
            #pragma unroll
            for (int g = 0; g < 8; g++) {
                int e = g * 32 + tx;
                bool better = (val[g] > bv) || (val[g] == bv && e < be);
                if (better) { bv = val[g]; be = e; }
            }
            #pragma unroll
            for (int off = 16; off > 0; off >>= 1) {
                float ov = __shfl_xor_sync(FULL, bv, off);
                int   oe = __shfl_xor_sync(FULL, be, off);
                if (ov > bv || (ov == bv && oe < be)) { bv = ov; be = oe; }
            }
            const int cg = be >> 5, cl = be & 31;
            float sel = lgv[0];
            #pragma unroll
            for (int g = 1; g < 8; g++) if (g == cg) sel = lgv[g];
            float lg = __shfl_sync(FULL, sel, cl);
            float wgt = sigmoid_acc(lg);
            wts[k] = wgt; ids[k] = be; wsum += wgt;
            #pragma unroll
            for (int g = 0; g < 8; g++)
                if (g == cg && tx == cl) val[g] = -3.4e38f;
        }

        if (tx == 0) {
            float denom = wsum + 1e-20f;
            #pragma unroll
            for (int k = 0; k < 8; k++) {
                out[(size_t)tok * 8 + k] = (float)ids[k];
                out[(size_t)TK * 8 + (size_t)tok * 8 + k] = (wts[k] / denom) * 2.5f;
            }
        }
    }
}

extern "C" void kernel_launch(void* const* d_in, const int* in_sizes, int n_in,
                              void* d_out, int out_size)
{
    const float* X    = (const float*)d_in[0];   // [4,4096,7168] fp32
    const float* W    = (const float*)d_in[1];   // [256,7168]    fp32
    const float* BIAS = (const float*)d_in[2];   // [256]         fp32
    float* out = (float*)d_out;                  // idx block then weight block

    cudaFuncSetAttribute(gemm_kernel,
                         cudaFuncAttributeMaxDynamicSharedMemorySize,
                         SMEM_FLOATS * (int)sizeof(float));

    float* L = g_L;   // __device__ scratch — resolve address host-side? No:
    // __device__ symbols can't be passed directly; take address via kernel arg
    // trick is unnecessary: pass nullptr and use g_L inside? Simplest: pass
    // the symbol through cudaGetSymbolAddress (host API, allocation-free).
    void* lptr = nullptr;
    cudaGetSymbolAddress(&lptr, g_L);
    L = (float*)lptr;

    dim3 grid(TK / BT, NE / BE);
    gemm_kernel<<<grid, 256, SMEM_FLOATS * sizeof(float)>>>(X, W, L);
    route_kernel<<<TK / 32, 256>>>(BIAS, out);
}